// round 14
// baseline (speedup 1.0000x reference)
#include <cuda_runtime.h>
#include <cuda_fp16.h>
#include <cstdint>

#define M_TOK 64
#define N_OUT 8192
#define K_IN  8192
#define NG    64            // K groups per row (8192/128)
#define NTILES (N_OUT / 64) // 128
#define WTOTAL (NTILES * NG)// 8192 work units
#define NCTA  296           // 2 per SM on 148 SMs
#define BN    64
#define BK    128
#define LDK   136           // Bs row stride in halves
#define NTHREADS 512        // 8 consumer warps + 8 producer warps
#define RING  3
#define ASTG  16384         // 64 rows x 256 B (XOR-swizzled x fp16)
#define BSTG  (BN * LDK * 2)// 17408
#define AS_OFF 0
#define BS_OFF (RING * ASTG)             // 49152
#define MB_OFF (BS_OFF + RING * BSTG)    // 101376
#define SMEM_BYTES (MB_OFF + 64)         // 101440 -> 2 CTA/SM

__device__ __half   g_xh[M_TOK * K_IN];      // x in fp16 (1 MB)
__device__ uint32_t g_szp[NG * N_OUT];       // packed (s,z) half2 (2 MB)
__device__ float    g_part[NCTA * 2 * 4096]; // stream-K partials

__device__ __forceinline__ int gsplit(int c) { return (int)(((long long)c * WTOTAL) / NCTA); }

// ---- prep: convert x to fp16 + pack (s,z) to half2; 16 floats/thread ----
__global__ void prep_kernel(const float* __restrict__ x, const float* __restrict__ sz) {
    const int NX = M_TOK * K_IN / 16;
    int t = blockIdx.x * blockDim.x + threadIdx.x;
    const float* src = (t < NX) ? (x + (size_t)t * 16) : (sz + (size_t)(t - NX) * 16);
    uint32_t* dst = (t < NX) ? reinterpret_cast<uint32_t*>(g_xh + (size_t)t * 16)
                             : (g_szp + (size_t)(t - NX) * 8);
    float4 v0 = *reinterpret_cast<const float4*>(src);
    float4 v1 = *reinterpret_cast<const float4*>(src + 4);
    float4 v2 = *reinterpret_cast<const float4*>(src + 8);
    float4 v3 = *reinterpret_cast<const float4*>(src + 12);
    __half2 h0 = __floats2half2_rn(v0.x, v0.y);
    __half2 h1 = __floats2half2_rn(v0.z, v0.w);
    __half2 h2 = __floats2half2_rn(v1.x, v1.y);
    __half2 h3 = __floats2half2_rn(v1.z, v1.w);
    __half2 h4 = __floats2half2_rn(v2.x, v2.y);
    __half2 h5 = __floats2half2_rn(v2.z, v2.w);
    __half2 h6 = __floats2half2_rn(v3.x, v3.y);
    __half2 h7 = __floats2half2_rn(v3.z, v3.w);
    uint4 pa, pb;
    pa.x = *reinterpret_cast<uint32_t*>(&h0);
    pa.y = *reinterpret_cast<uint32_t*>(&h1);
    pa.z = *reinterpret_cast<uint32_t*>(&h2);
    pa.w = *reinterpret_cast<uint32_t*>(&h3);
    pb.x = *reinterpret_cast<uint32_t*>(&h4);
    pb.y = *reinterpret_cast<uint32_t*>(&h5);
    pb.z = *reinterpret_cast<uint32_t*>(&h6);
    pb.w = *reinterpret_cast<uint32_t*>(&h7);
    *reinterpret_cast<uint4*>(dst)     = pa;
    *reinterpret_cast<uint4*>(dst + 4) = pb;
}

// ---- stream-K reduce ----
__global__ void reduce_kernel(float* __restrict__ out) {
    int i2 = (blockIdx.x * blockDim.x + threadIdx.x) * 2;
    int m  = i2 >> 13;
    int n  = i2 & (N_OUT - 1);
    int nt = n >> 6, nl = n & 63;
    int X  = nt << 6;
    int c  = (int)(((long long)X * NCTA) >> 13);
    while (gsplit(c + 1) <= X) ++c;
    float sx = 0.f, sy = 0.f;
    while (c < NCTA && gsplit(c) < X + 64) {
        int seg = ((gsplit(c) >> 6) == nt) ? 0 : 1;
        const float2 v = *reinterpret_cast<const float2*>(
            g_part + ((size_t)c * 2 + seg) * 4096 + m * 64 + nl);
        sx += v.x; sy += v.y;
        ++c;
    }
    *reinterpret_cast<float2*>(out + i2) = make_float2(sx, sy);
}

__device__ __forceinline__ void cp16(uint32_t dst, const void* src) {
    asm volatile("cp.async.cg.shared.global [%0], [%1], 16;" :: "r"(dst), "l"(src));
}
__device__ __forceinline__ void mbar_wait(uint32_t mbar, uint32_t parity) {
    asm volatile(
        "{\n\t.reg .pred P;\n\t"
        "WL%=:\n\t"
        "mbarrier.try_wait.parity.acquire.cta.shared::cta.b64 P, [%0], %1, 0x989680;\n\t"
        "@!P bra WL%=;\n\t}"
        :: "r"(mbar), "r"(parity) : "memory");
}
__device__ __forceinline__ void mbar_arrive(uint32_t mbar) {
    asm volatile("mbarrier.arrive.release.cta.shared::cta.b64 _, [%0];"
                 :: "r"(mbar) : "memory");
}
__device__ __forceinline__ void ldsm4(uint32_t& r0, uint32_t& r1, uint32_t& r2, uint32_t& r3,
                                      uint32_t a) {
    asm volatile("ldmatrix.sync.aligned.m8n8.x4.shared.b16 {%0,%1,%2,%3}, [%4];"
                 : "=r"(r0), "=r"(r1), "=r"(r2), "=r"(r3) : "r"(a));
}
__device__ __forceinline__ void mma_16816(float c[4],
                                          uint32_t a0, uint32_t a1, uint32_t a2, uint32_t a3,
                                          uint32_t b0, uint32_t b1) {
    asm volatile("mma.sync.aligned.m16n8k16.row.col.f32.f16.f16.f32 "
                 "{%0,%1,%2,%3}, {%4,%5,%6,%7}, {%8,%9}, {%0,%1,%2,%3};"
                 : "+f"(c[0]), "+f"(c[1]), "+f"(c[2]), "+f"(c[3])
                 : "r"(a0), "r"(a1), "r"(a2), "r"(a3), "r"(b0), "r"(b1));
}

__global__ void __launch_bounds__(NTHREADS, 2)
woq_gemm_kernel(const int* __restrict__ qw)
{
    extern __shared__ char smem[];
    const uint32_t s_base = (uint32_t)__cvta_generic_to_shared(smem);

    const int tid  = threadIdx.x;
    const int lane = tid & 31;
    const int warp = tid >> 5;
    const int cta  = blockIdx.x;
    const int w0 = gsplit(cta);
    const int w1 = gsplit(cta + 1);
    const int nch = w1 - w0;

    // mbarriers: FULL(s) = MB+s*16, EMPTY(s) = MB+s*16+8; both count 256
    if (tid == 0) {
        #pragma unroll
        for (int s = 0; s < RING; ++s) {
            asm volatile("mbarrier.init.shared.b64 [%0], %1;"
                         :: "r"(s_base + MB_OFF + s * 16), "r"(256u) : "memory");
            asm volatile("mbarrier.init.shared.b64 [%0], %1;"
                         :: "r"(s_base + MB_OFF + s * 16 + 8), "r"(256u) : "memory");
        }
    }
    __syncthreads();   // last CTA-wide barrier; roles diverge below

    const __half2 k1032 = __floats2half2_rn(1032.f, 1032.f);

    if (warp >= 8) {
        // ================= PRODUCER (warps 8..15, 256 threads) =================
        const int pw = warp - 8;            // 0..7 -> rows pw*8 + j
        const int ptid = tid - 256;         // 0..255
        // As cp.async mapping: row = ptid>>2 (0..63), units u0=(ptid&3)*4..+3
        const int arow = ptid >> 2;
        const int au0  = (ptid & 3) * 4;
        const __half* axsrc = g_xh + (size_t)arow * K_IN;
        // wq LDG: instr j -> row pw*8+j, lane covers 16B (4 q) at cols lane*4
        const int* qbase = qw + (size_t)(pw * 8) * K_IN + lane * 4;

        int s = 0;
        uint32_t par = 1;   // producer starts phase 1: first empty-wait passes
        for (int i = 0; i < nch; ++i) {
            const int w  = w0 + i;
            const int g  = w & (NG - 1);
            const int nb = (w >> 6) << 6;
            const int k0 = g * BK;

            mbar_wait(s_base + MB_OFF + s * 16 + 8, par);   // EMPTY(s)

            // issue weight LDGs (coalesced 512B per instr)
            int4 wq[8];
            const int* qr = qbase + (size_t)nb * K_IN + k0;
            #pragma unroll
            for (int j = 0; j < 8; ++j)
                wq[j] = *reinterpret_cast<const int4*>(qr + (size_t)j * K_IN);
            uint32_t szr[8];
            const uint32_t* szp = g_szp + (size_t)g * N_OUT + nb + pw * 8;
            #pragma unroll
            for (int j = 0; j < 8; ++j)
                szr[j] = szp[j];

            // issue As cp.async (XOR-swizzled rows of 256B)
            {
                const uint32_t dstrow = s_base + AS_OFF + s * ASTG + arow * 256;
                const __half* src = axsrc + k0;
                #pragma unroll
                for (int j = 0; j < 4; ++j) {
                    const int u = au0 + j;
                    cp16(dstrow + ((u ^ (arow & 7)) << 4), src + u * 8);
                }
                asm volatile("cp.async.commit_group;");
            }

            // dequant -> Bs[s]
            __half* Bsb = reinterpret_cast<__half*>(smem + BS_OFF + s * BSTG);
            #pragma unroll
            for (int j = 0; j < 8; ++j) {
                const int row = pw * 8 + j;
                const __half2 szh = *reinterpret_cast<const __half2*>(&szr[j]);
                const __half2 s2 = __half2half2(__low2half(szh));
                const __half2 z2 = __half2half2(__high2half(szh));
                const int4 q = wq[j];
                uint32_t p0 = 0x64006400u | (uint32_t)q.x | ((uint32_t)q.y << 16);
                uint32_t p1 = 0x64006400u | (uint32_t)q.z | ((uint32_t)q.w << 16);
                __half2 h0 = __hsub2(*reinterpret_cast<const __half2*>(&p0), k1032);
                __half2 h1 = __hsub2(*reinterpret_cast<const __half2*>(&p1), k1032);
                __half2 w0h = __hfma2(h0, s2, z2);
                __half2 w1h = __hfma2(h1, s2, z2);
                uint2 pk;
                pk.x = *reinterpret_cast<uint32_t*>(&w0h);
                pk.y = *reinterpret_cast<uint32_t*>(&w1h);
                *reinterpret_cast<uint2*>(&Bsb[row * LDK + lane * 4]) = pk;
            }

            asm volatile("cp.async.wait_group 0;");   // As(s) landed
            mbar_arrive(s_base + MB_OFF + s * 16);    // FULL(s)

            if (++s == RING) { s = 0; par ^= 1; }
        }
    } else {
        // ================= CONSUMER (warps 0..7, 256 threads) =================
        const int wm = warp & 3;
        const int wn = warp >> 2;

        float acc[4][4];
        #pragma unroll
        for (int i = 0; i < 4; ++i)
            #pragma unroll
            for (int j = 0; j < 4; ++j) acc[i][j] = 0.f;

        // A frag addressing (XOR layout)
        const int a_row = wm * 16 + (lane & 15);
        const int a_hi  = lane >> 4;
        const int a_sw  = a_row & 7;
        const uint32_t a_rowb = s_base + AS_OFF + (uint32_t)a_row * 256;
        // B frag addressing (LDK=136 layout)
        const uint32_t b0r = s_base + BS_OFF +
            2u * ((wn * 32 + (lane & 7) + ((lane >> 4) << 3)) * LDK + ((lane >> 3) & 1) * 8);

        int s = 0;
        uint32_t par = 0;
        int seg = 0;
        for (int i = 0; i < nch; ++i) {
            const int w = w0 + i;

            mbar_wait(s_base + MB_OFF + s * 16, par);   // FULL(s)

            const uint32_t ar  = a_rowb + s * ASTG;
            const uint32_t bb0 = b0r + s * BSTG;
            const uint32_t bb1 = bb0 + 2u * 16 * LDK;
            #pragma unroll
            for (int kk = 0; kk < 8; ++kk) {
                uint32_t a0, a1, a2, a3;
                ldsm4(a0, a1, a2, a3, ar + (((kk * 2 + a_hi) ^ a_sw) << 4));
                uint32_t b0, b1, b2, b3, b4, b5, b6, b7;
                ldsm4(b0, b1, b2, b3, bb0 + kk * 32);
                ldsm4(b4, b5, b6, b7, bb1 + kk * 32);
                mma_16816(acc[0], a0, a1, a2, a3, b0, b1);
                mma_16816(acc[1], a0, a1, a2, a3, b2, b3);
                mma_16816(acc[2], a0, a1, a2, a3, b4, b5);
                mma_16816(acc[3], a0, a1, a2, a3, b6, b7);
            }

            mbar_arrive(s_base + MB_OFF + s * 16 + 8);  // EMPTY(s)

            // segment boundary: write partial 64x64 block straight from regs
            if (w + 1 == w1 || ((w + 1) >> 6) != (w >> 6)) {
                float* part = g_part + ((size_t)cta * 2 + seg) * 4096;
                const int row = wm * 16 + (lane >> 2);
                #pragma unroll
                for (int j = 0; j < 4; ++j) {
                    const int col = wn * 32 + j * 8 + (lane & 3) * 2;
                    *reinterpret_cast<float2*>(part + row * 64 + col) =
                        make_float2(acc[j][0], acc[j][1]);
                    *reinterpret_cast<float2*>(part + (row + 8) * 64 + col) =
                        make_float2(acc[j][2], acc[j][3]);
                    acc[j][0] = acc[j][1] = acc[j][2] = acc[j][3] = 0.f;
                }
                ++seg;
            }

            if (++s == RING) { s = 0; par ^= 1; }
        }
    }
}

extern "C" void kernel_launch(void* const* d_in, const int* in_sizes, int n_in,
                              void* d_out, int out_size) {
    const float* x  = (const float*)d_in[0];   // (64, 8192) fp32
    const int*   qw = (const int*)d_in[1];     // (8192, 8192) int32 in [0,15]
    const float* sz = (const float*)d_in[2];   // (64, 8192, 2) fp32
    float* out = (float*)d_out;                // (64, 8192) fp32

    static bool attr_set = false;
    if (!attr_set) {
        cudaFuncSetAttribute(woq_gemm_kernel,
                             cudaFuncAttributeMaxDynamicSharedMemorySize, SMEM_BYTES);
        attr_set = true;
    }

    const int n_prep = (M_TOK * K_IN / 16) + (NG * N_OUT / 8);
    prep_kernel<<<n_prep / 256, 256>>>(x, sz);
    woq_gemm_kernel<<<NCTA, NTHREADS, SMEM_BYTES>>>(qw);
    reduce_kernel<<<(M_TOK * N_OUT / 2) / 256, 256>>>(out);
}